// round 10
// baseline (speedup 1.0000x reference)
#include <cuda_runtime.h>
#include <math.h>
#include <float.h>

#define BB   32
#define SS   4096
#define INF_ 256
#define DD   64
#define KK   8
#define NROW (BB*SS)          // 131072
#define EPSN 1e-5f
#define CS   256              // S-chunk for fused iteration kernel
#define NCH  (SS/CS)          // 16

typedef unsigned long long ULL;

// ---------------- packed fp32x2 helpers (FFMA2 path) ----------------
__device__ __forceinline__ ULL pk2(float lo, float hi) {
    ULL r; asm("mov.b64 %0, {%1, %2};" : "=l"(r) : "f"(lo), "f"(hi)); return r;
}
__device__ __forceinline__ void fma2(ULL& d, ULL a, ULL b) {
    asm("fma.rn.f32x2 %0, %1, %2, %0;" : "+l"(d) : "l"(a), "l"(b));
}
__device__ __forceinline__ float2 upk2(ULL v) {
    float2 f; asm("mov.b64 {%0, %1}, %2;" : "=f"(f.x), "=f"(f.y) : "l"(v)); return f;
}

// ---------------- tf32 helpers ----------------
__device__ __forceinline__ float tf32_hi(float x) {
    unsigned u; asm("cvt.rna.tf32.f32 %0, %1;" : "=r"(u) : "f"(x));
    return __uint_as_float(u);
}
__device__ __forceinline__ void mma8(float4& d, float a0, float a1, float a2, float a3,
                                     float b0, float b1) {
    asm("mma.sync.aligned.m16n8k8.row.col.f32.tf32.tf32.f32 "
        "{%0,%1,%2,%3}, {%4,%5,%6,%7}, {%8,%9}, {%0,%1,%2,%3};"
        : "+f"(d.x), "+f"(d.y), "+f"(d.z), "+f"(d.w)
        : "r"(__float_as_uint(a0)), "r"(__float_as_uint(a1)),
          "r"(__float_as_uint(a2)), "r"(__float_as_uint(a3)),
          "r"(__float_as_uint(b0)), "r"(__float_as_uint(b1)));
}

// ---------------- scratch (device globals; no allocation allowed) ----------------
__device__ __align__(16) float g_k[NROW*DD];             // 33.5 MB
__device__ __align__(16) float g_v[NROW*DD];             // 33.5 MB
__device__ __align__(16) float g_q[BB*KK*DD];
__device__ __align__(16) float g_slots[BB*KK*DD];
__device__ __align__(16) float g_updp[NCH*BB*KK*DD];     // per-chunk partial Sum(e^s * v)
__device__ float g_cst[NCH*BB*KK*2];                     // per-chunk {max, sumexp}
__device__ float g_stats[BB*KK*2];                       // global {max, 1/sum}
__device__ float g_cb[2*DD];                             // b_ln @ [Wk|Wv]

// ---------------- init: slots broadcast + epilogue bias precompute ----------------
__global__ void k_init(const float* __restrict__ slot_emb,
                       const float* __restrict__ Wk, const float* __restrict__ Wv,
                       const float* __restrict__ lnb) {
    int t = blockIdx.x*blockDim.x + threadIdx.x;
    if (t < BB*KK*DD) g_slots[t] = slot_emb[t % (KK*DD)];
    if (t < 2*DD) {
        float s = 0.f;
        for (int i = 0; i < INF_; i++) {
            float w = (t < DD) ? Wk[i*DD + t] : Wv[i*DD + (t-DD)];
            s += lnb[i]*w;
        }
        g_cb[t] = s;
    }
}

// ---------------- phase 1: fused LN + K/V projection via tf32 mma (3-split) -------
// CTA tile: 128 rows x 128 cols, K=256. 8 warps in 4x2 grid; warp tile m32 x n64.
// SMEM tiles hold {hi,lo} float2 pairs in a k-permuted layout so each mma fragment
// is a single LDS.128.
__global__ __launch_bounds__(256) void k_proj(const float* __restrict__ x,
                                              const float* __restrict__ Wk,
                                              const float* __restrict__ Wv,
                                              const float* __restrict__ gln) {
    __shared__ __align__(16) float2 xs2[128][18];   // x-hat {hi,lo}, k-chunk of 16
    __shared__ __align__(16) float2 ws2[128][18];   // weights (g folded) {hi,lo}
    __shared__ float rm[128], rr[128], scb[128];

    int tid  = threadIdx.x;
    int row0 = blockIdx.x * 128;
    int wid  = tid >> 5, lane = tid & 31;
    int wm   = wid & 3;            // m offset wm*32
    int wn   = wid >> 2;           // n offset wn*64
    int t4   = lane & 3;
    int g8   = lane >> 2;

    // per-row mean / rstd (warp handles 16 rows)
    for (int j = 0; j < 16; j++) {
        int r = wid*16 + j;
        const float* xr = x + (size_t)(row0 + r)*INF_;
        float s = 0.f, s2 = 0.f;
        for (int i = lane; i < INF_; i += 32) { float v = xr[i]; s += v; s2 += v*v; }
        #pragma unroll
        for (int o = 16; o; o >>= 1) {
            s  += __shfl_xor_sync(0xffffffffu, s,  o);
            s2 += __shfl_xor_sync(0xffffffffu, s2, o);
        }
        if (lane == 0) {
            float m = s * (1.f/INF_);
            rm[r] = m;
            rr[r] = rsqrtf(s2*(1.f/INF_) - m*m + EPSN);
        }
    }
    if (tid < 128) scb[tid] = g_cb[tid];

    float4 acc[2][8];
    #pragma unroll
    for (int mt = 0; mt < 2; mt++)
        #pragma unroll
        for (int nt = 0; nt < 8; nt++) acc[mt][nt] = make_float4(0.f,0.f,0.f,0.f);

    for (int kc = 0; kc < INF_; kc += 16) {
        __syncthreads();
        // ---- stage A: x-hat tile 128 x 16, split, permuted store ----
        {
            int r = tid >> 1, hh = tid & 1;          // 8 cols: hh*8 .. hh*8+7
            const float* xp = x + (size_t)(row0 + r)*INF_ + kc + hh*8;
            float4 xa = *(const float4*)xp;
            float4 xb = *(const float4*)(xp + 4);
            float m = rm[r], rs = rr[r];
            float v[8] = {xa.x,xa.y,xa.z,xa.w,xb.x,xb.y,xb.z,xb.w};
            #pragma unroll
            for (int j = 0; j < 8; j++) {
                float xn = (v[j] - m)*rs;
                float hi = tf32_hi(xn);
                int pos = hh*8 + (j&3)*2 + (j>>2);
                xs2[r][pos] = make_float2(hi, xn - hi);
            }
        }
        // ---- stage B: weight tile 16 x 128 (g folded), split, permuted store ----
        {
            int c = tid >> 4;                        // 0..15 (k within chunk)
            int n0 = (tid & 15) * 8;                 // 0..120
            float gs = gln[kc + c];
            const float* wp = (n0 < DD) ? (Wk + (size_t)(kc+c)*DD + n0)
                                        : (Wv + (size_t)(kc+c)*DD + (n0 - DD));
            float4 wa = *(const float4*)wp;
            float4 wb = *(const float4*)(wp + 4);
            float v[8] = {wa.x,wa.y,wa.z,wa.w,wb.x,wb.y,wb.z,wb.w};
            int cc = c & 7;
            int pos = (c>>3)*8 + (cc&3)*2 + (cc>>2);
            #pragma unroll
            for (int j = 0; j < 8; j++) {
                float wv = gs * v[j];
                float hi = tf32_hi(wv);
                ws2[n0 + j][pos] = make_float2(hi, wv - hi);
            }
        }
        __syncthreads();
        // ---- 2 mma k-steps over this chunk ----
        #pragma unroll
        for (int h = 0; h < 2; h++) {
            float4 aA[2], aB[2];
            #pragma unroll
            for (int mt = 0; mt < 2; mt++) {
                aA[mt] = *(const float4*)&xs2[wm*32 + mt*16 + g8    ][h*8 + t4*2];
                aB[mt] = *(const float4*)&xs2[wm*32 + mt*16 + 8 + g8][h*8 + t4*2];
            }
            #pragma unroll
            for (int nt = 0; nt < 8; nt++) {
                float4 bv = *(const float4*)&ws2[wn*64 + nt*8 + g8][h*8 + t4*2];
                #pragma unroll
                for (int mt = 0; mt < 2; mt++) {
                    // hi*hi, hi*lo, lo*hi
                    mma8(acc[mt][nt], aA[mt].x, aB[mt].x, aA[mt].z, aB[mt].z, bv.x, bv.z);
                    mma8(acc[mt][nt], aA[mt].x, aB[mt].x, aA[mt].z, aB[mt].z, bv.y, bv.w);
                    mma8(acc[mt][nt], aA[mt].y, aB[mt].y, aA[mt].w, aB[mt].w, bv.x, bv.z);
                }
            }
        }
    }

    // ---- epilogue: add cb bias, write to g_k / g_v ----
    float* dst = (wn == 0) ? g_k : g_v;
    #pragma unroll
    for (int mt = 0; mt < 2; mt++) {
        int rb = row0 + wm*32 + mt*16 + g8;
        #pragma unroll
        for (int nt = 0; nt < 8; nt++) {
            int n  = wn*64 + nt*8 + t4*2;       // CTA column
            int col = (wn == 0) ? n : (n - DD);
            float b0 = scb[n], b1 = scb[n+1];
            float4 a = acc[mt][nt];
            *(float2*)&dst[(size_t)rb*DD + col]     = make_float2(a.x + b0, a.y + b1);
            *(float2*)&dst[(size_t)(rb+8)*DD + col] = make_float2(a.z + b0, a.w + b1);
        }
    }
}

// ---------------- slot LN + q projection (tiny) ----------------
__global__ void k_q(const float* __restrict__ Wq, const float* __restrict__ g,
                    const float* __restrict__ bb) {
    int row = blockIdx.x, d = threadIdx.x;   // 64 threads
    __shared__ float sn[64];
    __shared__ float red[2];
    float xv = g_slots[row*DD + d];
    int lane = d & 31, w = d >> 5;
    float s = xv;
    #pragma unroll
    for (int o = 16; o; o >>= 1) s += __shfl_xor_sync(0xffffffffu, s, o);
    if (lane == 0) red[w] = s;
    __syncthreads();
    float m = (red[0] + red[1]) * (1.f/DD);
    __syncthreads();
    float df = xv - m;
    float q2 = df*df;
    #pragma unroll
    for (int o = 16; o; o >>= 1) q2 += __shfl_xor_sync(0xffffffffu, q2, o);
    if (lane == 0) red[w] = q2;
    __syncthreads();
    float var = (red[0] + red[1]) * (1.f/DD);
    float rs = rsqrtf(var + EPSN);
    sn[d] = df*rs*g[d] + bb[d];
    __syncthreads();
    float acc = 0.f;
    #pragma unroll 8
    for (int j = 0; j < DD; j++) acc += sn[j]*Wq[j*DD + d];
    g_q[row*DD + d] = acc;
}

// ---------------- fused iteration: scores + chunk-softmax + partial updates ------
// grid (NCH, BB), 256 threads; 256-s chunk, all 8 slots; one s-position per thread.
__global__ __launch_bounds__(256) void k_iter(const int* __restrict__ mask,
                                              float* __restrict__ attn, int last) {
    __shared__ float qs[KK][64];      // 2 KB
    __shared__ float ps[KK][CS];      // 8 KB : raw scores, then probabilities
    int b = blockIdx.y, ch = blockIdx.x, s0 = ch*CS;
    int tid = threadIdx.x;

    ((float2*)qs)[tid] = ((const float2*)(g_q + b*KK*DD))[tid];
    __syncthreads();

    // ---- phase A: one s-position per thread, all 8 slots (FFMA2) ----
    const float* kr = g_k + ((size_t)(b*SS + s0 + tid))*DD;
    ULL acc[KK];
    #pragma unroll
    for (int sl = 0; sl < KK; sl++) acc[sl] = 0ull;
    #pragma unroll
    for (int i = 0; i < 16; i++) {
        ulonglong2 ka = *(const ulonglong2*)(kr + i*4);
        #pragma unroll
        for (int sl = 0; sl < KK; sl++) {
            ulonglong2 qp = *(const ulonglong2*)&qs[sl][i*4];   // warp-uniform broadcast
            fma2(acc[sl], qp.x, ka.x);
            fma2(acc[sl], qp.y, ka.y);
        }
    }
    int mk = mask[b*SS + s0 + tid];
    #pragma unroll
    for (int sl = 0; sl < KK; sl++) {
        float2 t = upk2(acc[sl]);
        float sc = (t.x + t.y) * 0.125f;
        if (mk == 0) sc = -3.402823466e38f;
        ps[sl][tid] = sc;
        if (last) attn[((size_t)(b*KK + sl))*SS + s0 + tid] = sc;
    }
    __syncthreads();

    // ---- phase B: per-slot chunk max + sumexp; ps -> exp(s - m) (warp per slot) ----
    {
        int w = tid >> 5, lane = tid & 31;
        float m = -FLT_MAX;
        #pragma unroll
        for (int j = 0; j < CS/32; j++) m = fmaxf(m, ps[w][lane + 32*j]);
        #pragma unroll
        for (int o = 16; o; o >>= 1) m = fmaxf(m, __shfl_xor_sync(0xffffffffu, m, o));
        float l = 0.f;
        #pragma unroll
        for (int j = 0; j < CS/32; j++) {
            float p = expf(ps[w][lane + 32*j] - m);
            ps[w][lane + 32*j] = p;
            l += p;
        }
        #pragma unroll
        for (int o = 16; o; o >>= 1) l += __shfl_xor_sync(0xffffffffu, l, o);
        if (lane == 0) {
            g_cst[((ch*BB + b)*KK + w)*2]     = m;
            g_cst[((ch*BB + b)*KK + w)*2 + 1] = l;
        }
    }
    __syncthreads();

    // ---- phase C: U_c[slot][d] = sum_s p * v  (8-wide MLP, 4 accumulators) ----
    {
        int dp = tid & 31;       // d-pair -> d = 2*dp
        int sl = tid >> 5;       // slot
        const float* vp = g_v + ((size_t)(b*SS + s0))*DD + 2*dp;
        ULL a0 = 0ull, a1 = 0ull, a2 = 0ull, a3 = 0ull;
        #pragma unroll 2
        for (int s = 0; s < CS; s += 8) {
            float4 pA = *(const float4*)&ps[sl][s];
            float4 pB = *(const float4*)&ps[sl][s+4];
            ULL v0 = *(const ULL*)(vp + (size_t)(s+0)*DD);
            ULL v1 = *(const ULL*)(vp + (size_t)(s+1)*DD);
            ULL v2 = *(const ULL*)(vp + (size_t)(s+2)*DD);
            ULL v3 = *(const ULL*)(vp + (size_t)(s+3)*DD);
            ULL v4 = *(const ULL*)(vp + (size_t)(s+4)*DD);
            ULL v5 = *(const ULL*)(vp + (size_t)(s+5)*DD);
            ULL v6 = *(const ULL*)(vp + (size_t)(s+6)*DD);
            ULL v7 = *(const ULL*)(vp + (size_t)(s+7)*DD);
            fma2(a0, pk2(pA.x,pA.x), v0);
            fma2(a1, pk2(pA.y,pA.y), v1);
            fma2(a2, pk2(pA.z,pA.z), v2);
            fma2(a3, pk2(pA.w,pA.w), v3);
            fma2(a0, pk2(pB.x,pB.x), v4);
            fma2(a1, pk2(pB.y,pB.y), v5);
            fma2(a2, pk2(pB.z,pB.z), v6);
            fma2(a3, pk2(pB.w,pB.w), v7);
        }
        float2 r0 = upk2(a0), r1 = upk2(a1), r2 = upk2(a2), r3 = upk2(a3);
        float2 r = make_float2((r0.x + r1.x) + (r2.x + r3.x),
                               (r0.y + r1.y) + (r2.y + r3.y));
        *(float2*)&g_updp[((size_t)(ch*BB + b)*KK + sl)*DD + 2*dp] = r;
    }
}

// ---------------- GRU cell with deterministic chunk-combine prologue ----------------
__global__ __launch_bounds__(192) void k_gru(const float* __restrict__ W_ih,
                                             const float* __restrict__ W_hh,
                                             const float* __restrict__ b_ih,
                                             const float* __restrict__ b_hh) {
    __shared__ float su[64], sh[64], gx[192], gh[192];
    int row = blockIdx.x, tid = threadIdx.x;   // row = b*KK + slot
    if (tid < 64) {
        float m = -FLT_MAX;
        #pragma unroll
        for (int ch = 0; ch < NCH; ch++)
            m = fmaxf(m, g_cst[(ch*BB*KK + row)*2]);
        float l = 0.f, U = 0.f;
        #pragma unroll
        for (int ch = 0; ch < NCH; ch++) {
            float w = expf(g_cst[(ch*BB*KK + row)*2] - m);
            l += g_cst[(ch*BB*KK + row)*2 + 1] * w;
            U += g_updp[((size_t)ch*BB*KK + row)*DD + tid] * w;
        }
        su[tid] = U / l;
        sh[tid] = g_slots[row*DD + tid];
        if (tid == 0) { g_stats[row*2] = m; g_stats[row*2+1] = 1.f/l; }
    }
    __syncthreads();
    float ax = b_ih[tid], ah = b_hh[tid];
    #pragma unroll 8
    for (int j = 0; j < 64; j++) {
        ax += su[j]*W_ih[j*192 + tid];
        ah += sh[j]*W_hh[j*192 + tid];
    }
    gx[tid] = ax; gh[tid] = ah;
    __syncthreads();
    if (tid < 64) {
        float r = 1.f/(1.f + expf(-(gx[tid]      + gh[tid])));
        float z = 1.f/(1.f + expf(-(gx[tid+64]   + gh[tid+64])));
        float n = tanhf(gx[tid+128] + r*gh[tid+128]);
        g_slots[row*DD + tid] = (1.f - z)*n + z*sh[tid];
    }
}

// ---------------- normalize raw scores in d_out into attn probabilities ----------------
__global__ __launch_bounds__(256) void k_attn(float* __restrict__ attn) {
    int row = blockIdx.x;
    float m  = g_stats[row*2];
    float rl = g_stats[row*2 + 1];
    float* a = attn + (size_t)row*SS;
    for (int i = threadIdx.x; i < SS; i += 256)
        a[i] = expf(a[i] - m) * rl;
}

// ---------------- final: write slots + validity mask ----------------
__global__ void k_final(const float* __restrict__ Wval, const float* __restrict__ bval,
                        float* __restrict__ out) {
    int row = blockIdx.x, d = threadIdx.x;   // 64 threads
    __shared__ float red[2];
    float s = g_slots[row*DD + d];
    out[row*DD + d] = s;
    float p = s*Wval[d];
    int lane = d & 31, w = d >> 5;
    #pragma unroll
    for (int o = 16; o; o >>= 1) p += __shfl_xor_sync(0xffffffffu, p, o);
    if (lane == 0) red[w] = p;
    __syncthreads();
    if (d == 0) {
        float v = red[0] + red[1] + bval[0];
        out[(size_t)BB*KK*DD + (size_t)BB*KK*SS + row] = (v > 0.f) ? 1.f : 0.f;
    }
}

// ---------------- launch ----------------
extern "C" void kernel_launch(void* const* d_in, const int* in_sizes, int n_in,
                              void* d_out, int out_size) {
    const float* inputs   = (const float*)d_in[0];
    const int*   mask     = (const int*)  d_in[1];
    const float* slot_emb = (const float*)d_in[2];
    const float* Wq       = (const float*)d_in[3];
    const float* Wk       = (const float*)d_in[4];
    const float* Wv       = (const float*)d_in[5];
    const float* W_ih     = (const float*)d_in[6];
    const float* W_hh     = (const float*)d_in[7];
    const float* b_ih     = (const float*)d_in[8];
    const float* b_hh     = (const float*)d_in[9];
    const float* ln_in_g  = (const float*)d_in[10];
    const float* ln_in_b  = (const float*)d_in[11];
    const float* ln_s_g   = (const float*)d_in[12];
    const float* ln_s_b   = (const float*)d_in[13];
    const float* Wval     = (const float*)d_in[14];
    const float* bval     = (const float*)d_in[15];
    float* out  = (float*)d_out;
    float* attn = out + BB*KK*DD;   // attn region of d_out doubles as raw-score scratch

    k_init<<<64, 256>>>(slot_emb, Wk, Wv, ln_in_b);
    k_proj<<<NROW/128, 256>>>(inputs, Wk, Wv, ln_in_g);
    for (int it = 0; it < 3; it++) {
        k_q<<<BB*KK, 64>>>(Wq, ln_s_g, ln_s_b);
        k_iter<<<dim3(NCH, BB), 256>>>(mask, attn, (it == 2) ? 1 : 0);
        k_gru<<<BB*KK, 192>>>(W_ih, W_hh, b_ih, b_hh);
    }
    k_attn<<<BB*KK, 256>>>(attn);
    k_final<<<BB*KK, 64>>>(Wval, bval, out);
}

// round 11
// speedup vs baseline: 1.8438x; 1.8438x over previous
#include <cuda_runtime.h>
#include <math.h>
#include <float.h>

#define BB   32
#define SS   4096
#define INF_ 256
#define DD   64
#define KK   8
#define NROW (BB*SS)          // 131072
#define EPSN 1e-5f
#define CS   128              // S-chunk for fused iteration kernel
#define NCH  (SS/CS)          // 32

typedef unsigned long long ULL;

// ---------------- packed fp32x2 helpers (FFMA2 path) ----------------
__device__ __forceinline__ ULL pk2(float lo, float hi) {
    ULL r; asm("mov.b64 %0, {%1, %2};" : "=l"(r) : "f"(lo), "f"(hi)); return r;
}
__device__ __forceinline__ void fma2(ULL& d, ULL a, ULL b) {
    asm("fma.rn.f32x2 %0, %1, %2, %0;" : "+l"(d) : "l"(a), "l"(b));
}
__device__ __forceinline__ float2 upk2(ULL v) {
    float2 f; asm("mov.b64 {%0, %1}, %2;" : "=f"(f.x), "=f"(f.y) : "l"(v)); return f;
}

// ---------------- scratch (device globals; no allocation allowed) ----------------
__device__ __align__(16) float g_k[NROW*DD];             // 33.5 MB
__device__ __align__(16) float g_v[NROW*DD];             // 33.5 MB
__device__ __align__(16) float g_q[BB*KK*DD];
__device__ __align__(16) float g_slots[BB*KK*DD];
__device__ __align__(16) float g_updp[NCH*BB*KK*DD];     // per-chunk partial Sum(e^s * v)
__device__ float g_cst[NCH*BB*KK*2];                     // per-chunk {max, sumexp}
__device__ float g_stats[BB*KK*2];                       // global {max, 1/sum}
__device__ float g_cb[2*DD];                             // b_ln @ [Wk|Wv]

// ---------------- init: slots broadcast + epilogue bias precompute ----------------
__global__ void k_init(const float* __restrict__ slot_emb,
                       const float* __restrict__ Wk, const float* __restrict__ Wv,
                       const float* __restrict__ lnb) {
    int t = blockIdx.x*blockDim.x + threadIdx.x;
    if (t < BB*KK*DD) g_slots[t] = slot_emb[t % (KK*DD)];
    if (t < 2*DD) {
        float s = 0.f;
        for (int i = 0; i < INF_; i++) {
            float w = (t < DD) ? Wk[i*DD + t] : Wv[i*DD + (t-DD)];
            s += lnb[i]*w;
        }
        g_cb[t] = s;
    }
}

// ---------------- phase 1: fused LN + K/V projection GEMM (wide FFMA2) ----------------
// CTA tile 128 rows x 128 cols, K-chunks of 16. 256 threads, thread tile 8x8.
// x-hat stored in SMEM as DUPLICATED float2 pairs -> A fragments load pre-packed
// (no mov.b64 in the inner loop). 2 CTAs/SM.
__global__ __launch_bounds__(256, 2) void k_proj(const float* __restrict__ x,
                                                 const float* __restrict__ Wk,
                                                 const float* __restrict__ Wv,
                                                 const float* __restrict__ gln) {
    __shared__ __align__(16) float2 xsd[16][128];   // [k][row] duplicated {v,v}, 16 KB
    __shared__ __align__(16) float  ws[16][128];    // [k][col] g folded, 8 KB
    __shared__ float rm[128], rr[128], scb[128];

    int tid  = threadIdx.x;
    int row0 = blockIdx.x * 128;
    int wid  = tid >> 5, lane = tid & 31;
    int tr   = tid >> 4;    // 0..15 -> rows tr*8..tr*8+7
    int tc   = tid & 15;    // 0..15 -> cols tc*8..tc*8+7

    // per-row mean / rstd (warp handles 16 rows)
    for (int j = 0; j < 16; j++) {
        int r = wid*16 + j;
        const float* xr = x + (size_t)(row0 + r)*INF_;
        float s = 0.f, s2 = 0.f;
        for (int i = lane; i < INF_; i += 32) { float v = xr[i]; s += v; s2 += v*v; }
        #pragma unroll
        for (int o = 16; o; o >>= 1) {
            s  += __shfl_xor_sync(0xffffffffu, s,  o);
            s2 += __shfl_xor_sync(0xffffffffu, s2, o);
        }
        if (lane == 0) {
            float m = s * (1.f/INF_);
            rm[r] = m;
            rr[r] = rsqrtf(s2*(1.f/INF_) - m*m + EPSN);
        }
    }
    if (tid < 128) scb[tid] = g_cb[tid];
    __syncthreads();

    ULL acc[8][4];
    #pragma unroll
    for (int i = 0; i < 8; i++)
        #pragma unroll
        for (int c = 0; c < 4; c++) acc[i][c] = 0ull;

    for (int kc = 0; kc < INF_; kc += 16) {
        // stage A: x-hat 128 x 16, duplicated-pair store
        {
            int r = tid >> 1, c0 = (tid & 1)*8;
            const float* xp = x + (size_t)(row0 + r)*INF_ + kc + c0;
            float4 xa = *(const float4*)xp;
            float4 xb = *(const float4*)(xp + 4);
            float m = rm[r], rs = rr[r];
            float v[8] = {xa.x,xa.y,xa.z,xa.w,xb.x,xb.y,xb.z,xb.w};
            #pragma unroll
            for (int j = 0; j < 8; j++) {
                float xn = (v[j] - m)*rs;
                xsd[c0 + j][r] = make_float2(xn, xn);
            }
        }
        // stage B: weights 16 x 128 with g folded
        {
            int k  = tid >> 4;
            int n0 = (tid & 15)*8;
            float gs = gln[kc + k];
            const float* wp = (n0 < DD) ? (Wk + (size_t)(kc+k)*DD + n0)
                                        : (Wv + (size_t)(kc+k)*DD + (n0 - DD));
            float4 wa = *(const float4*)wp;
            float4 wb = *(const float4*)(wp + 4);
            *(float4*)&ws[k][n0]     = make_float4(gs*wa.x, gs*wa.y, gs*wa.z, gs*wa.w);
            *(float4*)&ws[k][n0 + 4] = make_float4(gs*wb.x, gs*wb.y, gs*wb.z, gs*wb.w);
        }
        __syncthreads();
        #pragma unroll
        for (int kk = 0; kk < 16; kk++) {
            const ulonglong2* ap = (const ulonglong2*)&xsd[kk][tr*8];
            ulonglong2 a0 = ap[0], a1 = ap[1], a2 = ap[2], a3 = ap[3];
            const ulonglong2* bp = (const ulonglong2*)&ws[kk][tc*8];
            ulonglong2 b01 = bp[0], b23 = bp[1];
            ULL A[8] = {a0.x, a0.y, a1.x, a1.y, a2.x, a2.y, a3.x, a3.y};
            ULL Bp[4] = {b01.x, b01.y, b23.x, b23.y};
            #pragma unroll
            for (int i = 0; i < 8; i++) {
                fma2(acc[i][0], A[i], Bp[0]);
                fma2(acc[i][1], A[i], Bp[1]);
                fma2(acc[i][2], A[i], Bp[2]);
                fma2(acc[i][3], A[i], Bp[3]);
            }
        }
        __syncthreads();
    }

    // epilogue: add bias, write
    float* dst = (tc < 8) ? g_k : g_v;
    int col = (tc < 8) ? tc*8 : (tc - 8)*8;
    float bv[8];
    #pragma unroll
    for (int j = 0; j < 8; j++) bv[j] = scb[tc*8 + j];
    #pragma unroll
    for (int i = 0; i < 8; i++) {
        int r = row0 + tr*8 + i;
        float2 p0 = upk2(acc[i][0]), p1 = upk2(acc[i][1]);
        float2 p2 = upk2(acc[i][2]), p3 = upk2(acc[i][3]);
        float4 o0 = make_float4(p0.x+bv[0], p0.y+bv[1], p1.x+bv[2], p1.y+bv[3]);
        float4 o1 = make_float4(p2.x+bv[4], p2.y+bv[5], p3.x+bv[6], p3.y+bv[7]);
        *(float4*)&dst[(size_t)r*DD + col]     = o0;
        *(float4*)&dst[(size_t)r*DD + col + 4] = o1;
    }
}

// ---------------- slot LN + q projection (tiny) ----------------
__global__ void k_q(const float* __restrict__ Wq, const float* __restrict__ g,
                    const float* __restrict__ bb) {
    int row = blockIdx.x, d = threadIdx.x;   // 64 threads
    __shared__ float sn[64];
    __shared__ float red[2];
    float xv = g_slots[row*DD + d];
    int lane = d & 31, w = d >> 5;
    float s = xv;
    #pragma unroll
    for (int o = 16; o; o >>= 1) s += __shfl_xor_sync(0xffffffffu, s, o);
    if (lane == 0) red[w] = s;
    __syncthreads();
    float m = (red[0] + red[1]) * (1.f/DD);
    __syncthreads();
    float df = xv - m;
    float q2 = df*df;
    #pragma unroll
    for (int o = 16; o; o >>= 1) q2 += __shfl_xor_sync(0xffffffffu, q2, o);
    if (lane == 0) red[w] = q2;
    __syncthreads();
    float var = (red[0] + red[1]) * (1.f/DD);
    float rs = rsqrtf(var + EPSN);
    sn[d] = df*rs*g[d] + bb[d];
    __syncthreads();
    float acc = 0.f;
    #pragma unroll 8
    for (int j = 0; j < DD; j++) acc += sn[j]*Wq[j*DD + d];
    g_q[row*DD + d] = acc;
}

// ---------------- fused iteration: K staged in SMEM, V read once, coalesced ------
// grid (NCH, BB), 256 threads; 128-s chunk, all 8 slots.
__global__ __launch_bounds__(256) void k_iter(const int* __restrict__ mask,
                                              float* __restrict__ attn, int last) {
    __shared__ float  qs[KK][64];          // 2 KB
    __shared__ float  ks[CS][68];          // 34.8 KB (reused as partial buffer in phase C)
    __shared__ float  ps[KK][CS];          // 4 KB raw scores
    __shared__ __align__(16) float2 psd[CS][KK];   // 8 KB duplicated probabilities
    int b = blockIdx.y, ch = blockIdx.x, s0 = ch*CS;
    int tid = threadIdx.x, lane = tid & 31, w = tid >> 5;

    ((float2*)qs)[tid] = ((const float2*)(g_q + b*KK*DD))[tid];
    // stage K chunk: fully coalesced float4
    #pragma unroll
    for (int it = 0; it < 8; it++) {
        int f = tid + it*256;           // float4 index over 128x64
        int r = f >> 4, c = (f & 15)*4;
        float4 kv = *(const float4*)&g_k[((size_t)(b*SS + s0 + r))*DD + c];
        *(float4*)&ks[r][c] = kv;
    }
    __syncthreads();

    // phase A: scores from SMEM; thread (r, slot-group of 4)
    {
        int r = tid & 127, h = tid >> 7;
        ULL acc[4] = {0ull,0ull,0ull,0ull};
        #pragma unroll
        for (int i = 0; i < 16; i++) {
            ulonglong2 kv = *(const ulonglong2*)&ks[r][i*4];
            #pragma unroll
            for (int sg = 0; sg < 4; sg++) {
                ulonglong2 qp = *(const ulonglong2*)&qs[h*4 + sg][i*4];  // warp-uniform
                fma2(acc[sg], qp.x, kv.x);
                fma2(acc[sg], qp.y, kv.y);
            }
        }
        int mk = mask[b*SS + s0 + r];
        #pragma unroll
        for (int sg = 0; sg < 4; sg++) {
            float2 t = upk2(acc[sg]);
            float sc = (t.x + t.y)*0.125f;
            if (mk == 0) sc = -3.402823466e38f;
            ps[h*4 + sg][r] = sc;
            if (last) attn[((size_t)(b*KK + h*4 + sg))*SS + s0 + r] = sc;
        }
    }
    __syncthreads();

    // phase B: warp w = slot w; chunk max + sumexp; write duplicated probs
    {
        float m = -FLT_MAX;
        #pragma unroll
        for (int j = 0; j < CS/32; j++) m = fmaxf(m, ps[w][lane + 32*j]);
        #pragma unroll
        for (int o = 16; o; o >>= 1) m = fmaxf(m, __shfl_xor_sync(0xffffffffu, m, o));
        float l = 0.f;
        #pragma unroll
        for (int j = 0; j < CS/32; j++) {
            float p = expf(ps[w][lane + 32*j] - m);
            psd[lane + 32*j][w] = make_float2(p, p);
            l += p;
        }
        #pragma unroll
        for (int o = 16; o; o >>= 1) l += __shfl_xor_sync(0xffffffffu, l, o);
        if (lane == 0) {
            g_cst[((ch*BB + b)*KK + w)*2]     = m;
            g_cst[((ch*BB + b)*KK + w)*2 + 1] = l;
        }
    }
    __syncthreads();

    // phase C: warp w handles s rows w*16..+16 for ALL slots; V read once, coalesced
    {
        const float* vp = g_v + ((size_t)(b*SS + s0 + w*16))*DD + 2*lane;
        ULL acc[8];
        #pragma unroll
        for (int sl = 0; sl < 8; sl++) acc[sl] = 0ull;
        #pragma unroll
        for (int s = 0; s < 16; s++) {
            ULL vv = *(const ULL*)(vp + (size_t)s*DD);
            const ulonglong2* pp = (const ulonglong2*)&psd[w*16 + s][0];  // warp-uniform
            ulonglong2 pA = pp[0], pB = pp[1], pC = pp[2], pD = pp[3];
            fma2(acc[0], pA.x, vv); fma2(acc[1], pA.y, vv);
            fma2(acc[2], pB.x, vv); fma2(acc[3], pB.y, vv);
            fma2(acc[4], pC.x, vv); fma2(acc[5], pC.y, vv);
            fma2(acc[6], pD.x, vv); fma2(acc[7], pD.y, vv);
        }
        float* pt = &ks[0][0];   // reuse staged-K buffer for partials: [warp][slot][64]
        #pragma unroll
        for (int sl = 0; sl < 8; sl++)
            *(float2*)&pt[(w*8 + sl)*64 + 2*lane] = upk2(acc[sl]);
    }
    __syncthreads();

    // reduce 8 warp partials in fixed order (deterministic)
    {
        int sl = tid >> 5, dp = lane;
        const float* pt = &ks[0][0];
        float sx = 0.f, sy = 0.f;
        #pragma unroll
        for (int ww = 0; ww < 8; ww++) {
            float2 p = *(const float2*)&pt[(ww*8 + sl)*64 + 2*dp];
            sx += p.x; sy += p.y;
        }
        *(float2*)&g_updp[((size_t)(ch*BB + b)*KK + sl)*DD + 2*dp] = make_float2(sx, sy);
    }
}

// ---------------- GRU cell with deterministic chunk-combine prologue ----------------
__global__ __launch_bounds__(192) void k_gru(const float* __restrict__ W_ih,
                                             const float* __restrict__ W_hh,
                                             const float* __restrict__ b_ih,
                                             const float* __restrict__ b_hh) {
    __shared__ float su[64], sh[64], gx[192], gh[192];
    int row = blockIdx.x, tid = threadIdx.x;   // row = b*KK + slot
    if (tid < 64) {
        float m = -FLT_MAX;
        #pragma unroll
        for (int ch = 0; ch < NCH; ch++)
            m = fmaxf(m, g_cst[(ch*BB*KK + row)*2]);
        float l = 0.f, U = 0.f;
        #pragma unroll
        for (int ch = 0; ch < NCH; ch++) {
            float wgt = expf(g_cst[(ch*BB*KK + row)*2] - m);
            l += g_cst[(ch*BB*KK + row)*2 + 1] * wgt;
            U += g_updp[((size_t)ch*BB*KK + row)*DD + tid] * wgt;
        }
        su[tid] = U / l;
        sh[tid] = g_slots[row*DD + tid];
        if (tid == 0) { g_stats[row*2] = m; g_stats[row*2+1] = 1.f/l; }
    }
    __syncthreads();
    float ax = b_ih[tid], ah = b_hh[tid];
    #pragma unroll 8
    for (int j = 0; j < 64; j++) {
        ax += su[j]*W_ih[j*192 + tid];
        ah += sh[j]*W_hh[j*192 + tid];
    }
    gx[tid] = ax; gh[tid] = ah;
    __syncthreads();
    if (tid < 64) {
        float r = 1.f/(1.f + expf(-(gx[tid]      + gh[tid])));
        float z = 1.f/(1.f + expf(-(gx[tid+64]   + gh[tid+64])));
        float n = tanhf(gx[tid+128] + r*gh[tid+128]);
        g_slots[row*DD + tid] = (1.f - z)*n + z*sh[tid];
    }
}

// ---------------- normalize raw scores in d_out into attn probabilities ----------------
__global__ __launch_bounds__(256) void k_attn(float* __restrict__ attn) {
    int row = blockIdx.x;
    float m  = g_stats[row*2];
    float rl = g_stats[row*2 + 1];
    float* a = attn + (size_t)row*SS;
    for (int i = threadIdx.x; i < SS; i += 256)
        a[i] = expf(a[i] - m) * rl;
}

// ---------------- final: write slots + validity mask ----------------
__global__ void k_final(const float* __restrict__ Wval, const float* __restrict__ bval,
                        float* __restrict__ out) {
    int row = blockIdx.x, d = threadIdx.x;   // 64 threads
    __shared__ float red[2];
    float s = g_slots[row*DD + d];
    out[row*DD + d] = s;
    float p = s*Wval[d];
    int lane = d & 31, w = d >> 5;
    #pragma unroll
    for (int o = 16; o; o >>= 1) p += __shfl_xor_sync(0xffffffffu, p, o);
    if (lane == 0) red[w] = p;
    __syncthreads();
    if (d == 0) {
        float v = red[0] + red[1] + bval[0];
        out[(size_t)BB*KK*DD + (size_t)BB*KK*SS + row] = (v > 0.f) ? 1.f : 0.f;
    }
}

// ---------------- launch ----------------
extern "C" void kernel_launch(void* const* d_in, const int* in_sizes, int n_in,
                              void* d_out, int out_size) {
    const float* inputs   = (const float*)d_in[0];
    const int*   mask     = (const int*)  d_in[1];
    const float* slot_emb = (const float*)d_in[2];
    const float* Wq       = (const float*)d_in[3];
    const float* Wk       = (const float*)d_in[4];
    const float* Wv       = (const float*)d_in[5];
    const float* W_ih     = (const float*)d_in[6];
    const float* W_hh     = (const float*)d_in[7];
    const float* b_ih     = (const float*)d_in[8];
    const float* b_hh     = (const float*)d_in[9];
    const float* ln_in_g  = (const float*)d_in[10];
    const float* ln_in_b  = (const float*)d_in[11];
    const float* ln_s_g   = (const float*)d_in[12];
    const float* ln_s_b   = (const float*)d_in[13];
    const float* Wval     = (const float*)d_in[14];
    const float* bval     = (const float*)d_in[15];
    float* out  = (float*)d_out;
    float* attn = out + BB*KK*DD;   // attn region of d_out doubles as raw-score scratch

    k_init<<<64, 256>>>(slot_emb, Wk, Wv, ln_in_b);
    k_proj<<<NROW/128, 256>>>(inputs, Wk, Wv, ln_in_g);
    for (int it = 0; it < 3; it++) {
        k_q<<<BB*KK, 64>>>(Wq, ln_s_g, ln_s_b);
        k_iter<<<dim3(NCH, BB), 256>>>(mask, attn, (it == 2) ? 1 : 0);
        k_gru<<<BB*KK, 192>>>(W_ih, W_hh, b_ih, b_hh);
    }
    k_attn<<<BB*KK, 256>>>(attn);
    k_final<<<BB*KK, 64>>>(Wval, bval, out);
}

// round 13
// speedup vs baseline: 2.7105x; 1.4701x over previous
#include <cuda_runtime.h>
#include <cuda_bf16.h>
#include <mma.h>
#include <math.h>
#include <float.h>
#include <stdint.h>

using namespace nvcuda;

#define BB   32
#define SS   4096
#define INF_ 256
#define DD   64
#define KK   8
#define NROW (BB*SS)          // 131072
#define EPSN 1e-5f
#define CS   128              // S-chunk for fused iteration kernel
#define NCH  (SS/CS)          // 32

typedef unsigned long long ULL;

// ---------------- packed fp32x2 helpers (FFMA2 path) ----------------
__device__ __forceinline__ ULL pk2(float lo, float hi) {
    ULL r; asm("mov.b64 %0, {%1, %2};" : "=l"(r) : "f"(lo), "f"(hi)); return r;
}
__device__ __forceinline__ void fma2(ULL& d, ULL a, ULL b) {
    asm("fma.rn.f32x2 %0, %1, %2, %0;" : "+l"(d) : "l"(a), "l"(b));
}
__device__ __forceinline__ float2 upk2(ULL v) {
    float2 f; asm("mov.b64 {%0, %1}, %2;" : "=f"(f.x), "=f"(f.y) : "l"(v)); return f;
}

// ---------------- scratch (device globals; no allocation allowed) ----------------
__device__ __align__(16) float g_k[NROW*DD];             // 33.5 MB
__device__ __align__(16) float g_v[NROW*DD];             // 33.5 MB
__device__ __align__(16) float g_q[BB*KK*DD];
__device__ __align__(16) float g_slots[BB*KK*DD];
__device__ __align__(16) float g_updp[NCH*BB*KK*DD];
__device__ float g_cst[NCH*BB*KK*2];
__device__ float g_stats[BB*KK*2];
__device__ float g_cb[2*DD];                             // b_ln @ [Wk|Wv] (exact fp32)
__device__ __align__(16) __nv_bfloat16 g_whT[128*INF_];  // split weights, transposed [n][k]
__device__ __align__(16) __nv_bfloat16 g_wlT[128*INF_];

// ---------------- init: slots broadcast + epilogue bias precompute ----------------
__global__ void k_init(const float* __restrict__ slot_emb,
                       const float* __restrict__ Wk, const float* __restrict__ Wv,
                       const float* __restrict__ lnb) {
    int t = blockIdx.x*blockDim.x + threadIdx.x;
    if (t < BB*KK*DD) g_slots[t] = slot_emb[t % (KK*DD)];
    if (t < 2*DD) {
        float s = 0.f;
        for (int i = 0; i < INF_; i++) {
            float w = (t < DD) ? Wk[i*DD + t] : Wv[i*DD + (t-DD)];
            s += lnb[i]*w;
        }
        g_cb[t] = s;
    }
}

// ---------------- weight split: [k][n] fp32 -> transposed bf16 hi/lo [n][k] ------
__global__ void k_wsplit(const float* __restrict__ Wk, const float* __restrict__ Wv,
                         const float* __restrict__ gln) {
    int idx = blockIdx.x*256 + threadIdx.x;     // over 128 n x 256 k
    int n = idx >> 8, k = idx & 255;
    float w = gln[k] * ((n < DD) ? Wk[k*DD + n] : Wv[k*DD + (n - DD)]);
    __nv_bfloat16 hi = __float2bfloat16(w);
    __nv_bfloat16 lo = __float2bfloat16(w - __bfloat162float(hi));
    g_whT[n*INF_ + k] = hi;
    g_wlT[n*INF_ + k] = lo;
}

// ---------------- phase 1: fused LN + K/V projection via wmma bf16 2-split -------
// CTA 128 rows x 128 cols (K||V), K=256 in 8 chunks of 32. 8 warps: 4m x 2n,
// warp tile m32 x n64. LN bias folded in as an extra k=16 GEMM step so acc
// fragments store straight to gmem.
#define LDP 40   // padded SMEM k-stride (bf16 elems); 80B row stride -> conflict-free LDSM

__global__ __launch_bounds__(256, 2) void k_proj(const float* __restrict__ x) {
    __shared__ __align__(16) __nv_bfloat16 Ah[128][LDP];
    __shared__ __align__(16) __nv_bfloat16 Al[128][LDP];
    __shared__ __align__(16) __nv_bfloat16 Bh[128][LDP];
    __shared__ __align__(16) __nv_bfloat16 Bl[128][LDP];
    __shared__ float rm[128], rr[128], scb[128];

    int tid = threadIdx.x, wid = tid >> 5, lane = tid & 31;
    int row0 = blockIdx.x * 128;
    int wm = wid & 3;       // m offset wm*32
    int wn = wid >> 2;      // n offset wn*64

    // per-row mean / rstd (warp handles 16 rows)
    for (int j = 0; j < 16; j++) {
        int r = wid*16 + j;
        const float* xr = x + (size_t)(row0 + r)*INF_;
        float s = 0.f, s2 = 0.f;
        for (int i = lane; i < INF_; i += 32) { float v = xr[i]; s += v; s2 += v*v; }
        #pragma unroll
        for (int o = 16; o; o >>= 1) {
            s  += __shfl_xor_sync(0xffffffffu, s,  o);
            s2 += __shfl_xor_sync(0xffffffffu, s2, o);
        }
        if (lane == 0) {
            float m = s * (1.f/INF_);
            rm[r] = m;
            rr[r] = rsqrtf(s2*(1.f/INF_) - m*m + EPSN);
        }
    }
    if (tid < 128) scb[tid] = g_cb[tid];

    wmma::fragment<wmma::accumulator, 16, 16, 16, float> acc[2][4];
    #pragma unroll
    for (int mt = 0; mt < 2; mt++)
        #pragma unroll
        for (int nt = 0; nt < 4; nt++) wmma::fill_fragment(acc[mt][nt], 0.f);

    int r_  = tid >> 1;          // staging row (A) / n (B)
    int kh  = (tid & 1) * 16;    // k half within chunk

    for (int c = 0; c < 8; c++) {
        __syncthreads();         // prev chunk's fragment loads complete
        // ---- stage A: x-hat 128x32, bf16 hi/lo split ----
        {
            float m = rm[r_], rs = rr[r_];
            const float* xp = x + (size_t)(row0 + r_)*INF_ + c*32 + kh;
            float4 v0 = *(const float4*)xp;
            float4 v1 = *(const float4*)(xp + 4);
            float4 v2 = *(const float4*)(xp + 8);
            float4 v3 = *(const float4*)(xp + 12);
            float vv[16] = {v0.x,v0.y,v0.z,v0.w, v1.x,v1.y,v1.z,v1.w,
                            v2.x,v2.y,v2.z,v2.w, v3.x,v3.y,v3.z,v3.w};
            uint32_t hw[8], lw[8];
            #pragma unroll
            for (int p = 0; p < 8; p++) {
                float a0 = (vv[2*p]   - m)*rs;
                float a1 = (vv[2*p+1] - m)*rs;
                __nv_bfloat16 h0 = __float2bfloat16(a0);
                __nv_bfloat16 h1 = __float2bfloat16(a1);
                __nv_bfloat162 hp(h0, h1);
                __nv_bfloat162 lp = __floats2bfloat162_rn(a0 - __bfloat162float(h0),
                                                          a1 - __bfloat162float(h1));
                hw[p] = *(uint32_t*)&hp;
                lw[p] = *(uint32_t*)&lp;
            }
            *(uint4*)&Ah[r_][kh]     = make_uint4(hw[0],hw[1],hw[2],hw[3]);
            *(uint4*)&Ah[r_][kh + 8] = make_uint4(hw[4],hw[5],hw[6],hw[7]);
            *(uint4*)&Al[r_][kh]     = make_uint4(lw[0],lw[1],lw[2],lw[3]);
            *(uint4*)&Al[r_][kh + 8] = make_uint4(lw[4],lw[5],lw[6],lw[7]);
        }
        // ---- stage B: split weights [n][k], direct copies ----
        {
            const __nv_bfloat16* wh = g_whT + r_*INF_ + c*32 + kh;
            const __nv_bfloat16* wl = g_wlT + r_*INF_ + c*32 + kh;
            uint4 h0 = *(const uint4*)wh, h1 = *(const uint4*)(wh + 8);
            uint4 l0 = *(const uint4*)wl, l1 = *(const uint4*)(wl + 8);
            *(uint4*)&Bh[r_][kh]     = h0;
            *(uint4*)&Bh[r_][kh + 8] = h1;
            *(uint4*)&Bl[r_][kh]     = l0;
            *(uint4*)&Bl[r_][kh + 8] = l1;
        }
        __syncthreads();

        #pragma unroll
        for (int ks = 0; ks < 2; ks++) {
            wmma::fragment<wmma::matrix_a, 16,16,16, __nv_bfloat16, wmma::row_major> ah[2], al[2];
            #pragma unroll
            for (int mt = 0; mt < 2; mt++) {
                wmma::load_matrix_sync(ah[mt], &Ah[wm*32 + mt*16][ks*16], LDP);
                wmma::load_matrix_sync(al[mt], &Al[wm*32 + mt*16][ks*16], LDP);
            }
            #pragma unroll
            for (int nt = 0; nt < 4; nt++) {
                wmma::fragment<wmma::matrix_b, 16,16,16, __nv_bfloat16, wmma::col_major> bh, bl;
                wmma::load_matrix_sync(bh, &Bh[wn*64 + nt*16][ks*16], LDP);
                wmma::load_matrix_sync(bl, &Bl[wn*64 + nt*16][ks*16], LDP);
                #pragma unroll
                for (int mt = 0; mt < 2; mt++) {
                    wmma::mma_sync(acc[mt][nt], ah[mt], bh, acc[mt][nt]);
                    wmma::mma_sync(acc[mt][nt], ah[mt], bl, acc[mt][nt]);
                    wmma::mma_sync(acc[mt][nt], al[mt], bh, acc[mt][nt]);
                }
            }
        }
    }

    // ---- bias k-step: A col0 = 1, B row0 = cb (hi/lo) ----
    __syncthreads();
    {
        __nv_bfloat16 one = __float2bfloat16(1.f);
        float cbv = scb[r_];
        __nv_bfloat16 ch = __float2bfloat16(cbv);
        __nv_bfloat16 cl = __float2bfloat16(cbv - __bfloat162float(ch));
        #pragma unroll
        for (int j = 0; j < 16; j++) {
            int kcol = kh + j;
            Ah[r_][kcol] = (kcol == 0) ? one : __float2bfloat16(0.f);
            Bh[r_][kcol] = (kcol == 0) ? ch  : __float2bfloat16(0.f);
            Bl[r_][kcol] = (kcol == 0) ? cl  : __float2bfloat16(0.f);
        }
    }
    __syncthreads();
    {
        wmma::fragment<wmma::matrix_a, 16,16,16, __nv_bfloat16, wmma::row_major> ah[2];
        #pragma unroll
        for (int mt = 0; mt < 2; mt++)
            wmma::load_matrix_sync(ah[mt], &Ah[wm*32 + mt*16][0], LDP);
        #pragma unroll
        for (int nt = 0; nt < 4; nt++) {
            wmma::fragment<wmma::matrix_b, 16,16,16, __nv_bfloat16, wmma::col_major> bh, bl;
            wmma::load_matrix_sync(bh, &Bh[wn*64 + nt*16][0], LDP);
            wmma::load_matrix_sync(bl, &Bl[wn*64 + nt*16][0], LDP);
            #pragma unroll
            for (int mt = 0; mt < 2; mt++) {
                wmma::mma_sync(acc[mt][nt], ah[mt], bh, acc[mt][nt]);
                wmma::mma_sync(acc[mt][nt], ah[mt], bl, acc[mt][nt]);
            }
        }
    }

    // ---- store fragments straight to g_k / g_v ----
    #pragma unroll
    for (int mt = 0; mt < 2; mt++) {
        int rb = row0 + wm*32 + mt*16;
        #pragma unroll
        for (int nt = 0; nt < 4; nt++) {
            int n = wn*64 + nt*16;
            float* dst = (n < DD) ? &g_k[(size_t)rb*DD + n]
                                  : &g_v[(size_t)rb*DD + (n - DD)];
            wmma::store_matrix_sync(dst, acc[mt][nt], DD, wmma::mem_row_major);
        }
    }
}

// ---------------- slot LN + q projection (tiny) ----------------
__global__ void k_q(const float* __restrict__ Wq, const float* __restrict__ g,
                    const float* __restrict__ bb) {
    int row = blockIdx.x, d = threadIdx.x;   // 64 threads
    __shared__ float sn[64];
    __shared__ float red[2];
    float xv = g_slots[row*DD + d];
    int lane = d & 31, w = d >> 5;
    float s = xv;
    #pragma unroll
    for (int o = 16; o; o >>= 1) s += __shfl_xor_sync(0xffffffffu, s, o);
    if (lane == 0) red[w] = s;
    __syncthreads();
    float m = (red[0] + red[1]) * (1.f/DD);
    __syncthreads();
    float df = xv - m;
    float q2 = df*df;
    #pragma unroll
    for (int o = 16; o; o >>= 1) q2 += __shfl_xor_sync(0xffffffffu, q2, o);
    if (lane == 0) red[w] = q2;
    __syncthreads();
    float var = (red[0] + red[1]) * (1.f/DD);
    float rs = rsqrtf(var + EPSN);
    sn[d] = df*rs*g[d] + bb[d];
    __syncthreads();
    float acc = 0.f;
    #pragma unroll 8
    for (int j = 0; j < DD; j++) acc += sn[j]*Wq[j*DD + d];
    g_q[row*DD + d] = acc;
}

// ---------------- fused iteration: K staged in SMEM, V read once, coalesced ------
__global__ __launch_bounds__(256) void k_iter(const int* __restrict__ mask,
                                              float* __restrict__ attn, int last) {
    __shared__ float  qs[KK][64];
    __shared__ float  ks[CS][68];
    __shared__ float  ps[KK][CS];
    __shared__ __align__(16) float2 psd[CS][KK];
    int b = blockIdx.y, ch = blockIdx.x, s0 = ch*CS;
    int tid = threadIdx.x, lane = tid & 31, w = tid >> 5;

    ((float2*)qs)[tid] = ((const float2*)(g_q + b*KK*DD))[tid];
    #pragma unroll
    for (int it = 0; it < 8; it++) {
        int f = tid + it*256;
        int r = f >> 4, c = (f & 15)*4;
        float4 kv = *(const float4*)&g_k[((size_t)(b*SS + s0 + r))*DD + c];
        *(float4*)&ks[r][c] = kv;
    }
    __syncthreads();

    {
        int r = tid & 127, h = tid >> 7;
        ULL acc[4] = {0ull,0ull,0ull,0ull};
        #pragma unroll
        for (int i = 0; i < 16; i++) {
            ulonglong2 kv = *(const ulonglong2*)&ks[r][i*4];
            #pragma unroll
            for (int sg = 0; sg < 4; sg++) {
                ulonglong2 qp = *(const ulonglong2*)&qs[h*4 + sg][i*4];
                fma2(acc[sg], qp.x, kv.x);
                fma2(acc[sg], qp.y, kv.y);
            }
        }
        int mk = mask[b*SS + s0 + r];
        #pragma unroll
        for (int sg = 0; sg < 4; sg++) {
            float2 t = upk2(acc[sg]);
            float sc = (t.x + t.y)*0.125f;
            if (mk == 0) sc = -3.402823466e38f;
            ps[h*4 + sg][r] = sc;
            if (last) attn[((size_t)(b*KK + h*4 + sg))*SS + s0 + r] = sc;
        }
    }
    __syncthreads();

    {
        float m = -FLT_MAX;
        #pragma unroll
        for (int j = 0; j < CS/32; j++) m = fmaxf(m, ps[w][lane + 32*j]);
        #pragma unroll
        for (int o = 16; o; o >>= 1) m = fmaxf(m, __shfl_xor_sync(0xffffffffu, m, o));
        float l = 0.f;
        #pragma unroll
        for (int j = 0; j < CS/32; j++) {
            float p = expf(ps[w][lane + 32*j] - m);
            psd[lane + 32*j][w] = make_float2(p, p);
            l += p;
        }
        #pragma unroll
        for (int o = 16; o; o >>= 1) l += __shfl_xor_sync(0xffffffffu, l, o);
        if (lane == 0) {
            g_cst[((ch*BB + b)*KK + w)*2]     = m;
            g_cst[((ch*BB + b)*KK + w)*2 + 1] = l;
        }
    }
    __syncthreads();

    {
        const float* vp = g_v + ((size_t)(b*SS + s0 + w*16))*DD + 2*lane;
        ULL acc[8];
        #pragma unroll
        for (int sl = 0; sl < 8; sl++) acc[sl] = 0ull;
        #pragma unroll
        for (int s = 0; s < 16; s++) {
            ULL vv = *(const ULL*)(vp + (size_t)s*DD);
            const ulonglong2* pp = (const ulonglong2*)&psd[w*16 + s][0];
            ulonglong2 pA = pp[0], pB = pp[1], pC = pp[2], pD = pp[3];
            fma2(acc[0], pA.x, vv); fma2(acc[1], pA.y, vv);
            fma2(acc[2], pB.x, vv); fma2(acc[3], pB.y, vv);
            fma2(acc[4], pC.x, vv); fma2(acc[5], pC.y, vv);
            fma2(acc[6], pD.x, vv); fma2(acc[7], pD.y, vv);
        }
        float* pt = &ks[0][0];
        #pragma unroll
        for (int sl = 0; sl < 8; sl++)
            *(float2*)&pt[(w*8 + sl)*64 + 2*lane] = upk2(acc[sl]);
    }
    __syncthreads();

    {
        int sl = tid >> 5, dp = lane;
        const float* pt = &ks[0][0];
        float sx = 0.f, sy = 0.f;
        #pragma unroll
        for (int ww = 0; ww < 8; ww++) {
            float2 p = *(const float2*)&pt[(ww*8 + sl)*64 + 2*dp];
            sx += p.x; sy += p.y;
        }
        *(float2*)&g_updp[((size_t)(ch*BB + b)*KK + sl)*DD + 2*dp] = make_float2(sx, sy);
    }
}

// ---------------- GRU cell with deterministic chunk-combine prologue ----------------
__global__ __launch_bounds__(192) void k_gru(const float* __restrict__ W_ih,
                                             const float* __restrict__ W_hh,
                                             const float* __restrict__ b_ih,
                                             const float* __restrict__ b_hh) {
    __shared__ float su[64], sh[64], gx[192], gh[192];
    int row = blockIdx.x, tid = threadIdx.x;
    if (tid < 64) {
        float m = -FLT_MAX;
        #pragma unroll
        for (int ch = 0; ch < NCH; ch++)
            m = fmaxf(m, g_cst[(ch*BB*KK + row)*2]);
        float l = 0.f, U = 0.f;
        #pragma unroll
        for (int ch = 0; ch < NCH; ch++) {
            float wgt = expf(g_cst[(ch*BB*KK + row)*2] - m);
            l += g_cst[(ch*BB*KK + row)*2 + 1] * wgt;
            U += g_updp[((size_t)ch*BB*KK + row)*DD + tid] * wgt;
        }
        su[tid] = U / l;
        sh[tid] = g_slots[row*DD + tid];
        if (tid == 0) { g_stats[row*2] = m; g_stats[row*2+1] = 1.f/l; }
    }
    __syncthreads();
    float ax = b_ih[tid], ah = b_hh[tid];
    #pragma unroll 8
    for (int j = 0; j < 64; j++) {
        ax += su[j]*W_ih[j*192 + tid];
        ah += sh[j]*W_hh[j*192 + tid];
    }
    gx[tid] = ax; gh[tid] = ah;
    __syncthreads();
    if (tid < 64) {
        float r = 1.f/(1.f + expf(-(gx[tid]      + gh[tid])));
        float z = 1.f/(1.f + expf(-(gx[tid+64]   + gh[tid+64])));
        float n = tanhf(gx[tid+128] + r*gh[tid+128]);
        g_slots[row*DD + tid] = (1.f - z)*n + z*sh[tid];
    }
}

// ---------------- normalize raw scores into attn probabilities ----------------
__global__ __launch_bounds__(256) void k_attn(float* __restrict__ attn) {
    int row = blockIdx.x;
    float m  = g_stats[row*2];
    float rl = g_stats[row*2 + 1];
    float* a = attn + (size_t)row*SS;
    for (int i = threadIdx.x; i < SS; i += 256)
        a[i] = expf(a[i] - m) * rl;
}

// ---------------- final: write slots + validity mask ----------------
__global__ void k_final(const float* __restrict__ Wval, const float* __restrict__ bval,
                        float* __restrict__ out) {
    int row = blockIdx.x, d = threadIdx.x;
    __shared__ float red[2];
    float s = g_slots[row*DD + d];
    out[row*DD + d] = s;
    float p = s*Wval[d];
    int lane = d & 31, w = d >> 5;
    #pragma unroll
    for (int o = 16; o; o >>= 1) p += __shfl_xor_sync(0xffffffffu, p, o);
    if (lane == 0) red[w] = p;
    __syncthreads();
    if (d == 0) {
        float v = red[0] + red[1] + bval[0];
        out[(size_t)BB*KK*DD + (size_t)BB*KK*SS + row] = (v > 0.f) ? 1.f : 0.f;
    }
}

// ---------------- launch ----------------
extern "C" void kernel_launch(void* const* d_in, const int* in_sizes, int n_in,
                              void* d_out, int out_size) {
    const float* inputs   = (const float*)d_in[0];
    const int*   mask     = (const int*)  d_in[1];
    const float* slot_emb = (const float*)d_in[2];
    const float* Wq       = (const float*)d_in[3];
    const float* Wk       = (const float*)d_in[4];
    const float* Wv       = (const float*)d_in[5];
    const float* W_ih     = (const float*)d_in[6];
    const float* W_hh     = (const float*)d_in[7];
    const float* b_ih     = (const float*)d_in[8];
    const float* b_hh     = (const float*)d_in[9];
    const float* ln_in_g  = (const float*)d_in[10];
    const float* ln_in_b  = (const float*)d_in[11];
    const float* ln_s_g   = (const float*)d_in[12];
    const float* ln_s_b   = (const float*)d_in[13];
    const float* Wval     = (const float*)d_in[14];
    const float* bval     = (const float*)d_in[15];
    float* out  = (float*)d_out;
    float* attn = out + BB*KK*DD;   // attn region of d_out doubles as raw-score scratch

    k_init<<<64, 256>>>(slot_emb, Wk, Wv, ln_in_b);
    k_wsplit<<<128, 256>>>(Wk, Wv, ln_in_g);
    k_proj<<<NROW/128, 256>>>(inputs);
    for (int it = 0; it < 3; it++) {
        k_q<<<BB*KK, 64>>>(Wq, ln_s_g, ln_s_b);
        k_iter<<<dim3(NCH, BB), 256>>>(mask, attn, (it == 2) ? 1 : 0);
        k_gru<<<BB*KK, 192>>>(W_ih, W_hh, b_ih, b_hh);
    }
    k_attn<<<BB*KK, 256>>>(attn);
    k_final<<<BB*KK, 64>>>(Wval, bval, out);
}